// round 8
// baseline (speedup 1.0000x reference)
#include <cuda_runtime.h>
#include <cuda_fp16.h>
#include <cuda_bf16.h>
#include <math.h>
#include <stdint.h>

#define BATCH 4
#define CDIM  256
#define CQK   32
#define NPIX  4096   // 64*64
#define MROWS 320    // 32 (Q) + 32 (K) + 256 (V)
#define LOG2E 1.4426950408889634f

// fp16 scratch (static device globals: allowed)
__device__ __half g_Qh[BATCH * NPIX * CQK];    // Q pre-scaled by log2(e)
__device__ __half g_Kh[BATCH * NPIX * CQK];
__device__ __half g_VhT[(size_t)BATCH * CDIM * NPIX];   // [B][C][N]
__device__ __half g_xhT[(size_t)BATCH * NPIX * CDIM];   // [B][N][C]
__device__ __half g_Wh[MROWS * CDIM];                   // Wq|Wk|Wv stacked
__device__ float  g_ball[MROWS];

// ---------------------------------------------------------------------------
// helpers (defined BEFORE all uses)
// ---------------------------------------------------------------------------
__device__ __forceinline__ uint32_t h2_as_u32(__half2 h)
{
    return *(uint32_t*)&h;
}

__device__ __forceinline__ float ex2(float x)
{
    float y;
    asm("ex2.approx.f32 %0, %1;" : "=f"(y) : "f"(x));
    return y;
}

__device__ __forceinline__ void mma16816(
    float& c0, float& c1, float& c2, float& c3,
    uint32_t a0, uint32_t a1, uint32_t a2, uint32_t a3,
    uint32_t b0, uint32_t b1)
{
    asm volatile(
        "mma.sync.aligned.m16n8k16.row.col.f32.f16.f16.f32 "
        "{%0,%1,%2,%3}, {%4,%5,%6,%7}, {%8,%9}, {%0,%1,%2,%3};\n"
        : "+f"(c0), "+f"(c1), "+f"(c2), "+f"(c3)
        : "r"(a0), "r"(a1), "r"(a2), "r"(a3), "r"(b0), "r"(b1));
}

__device__ __forceinline__ void ldsm_x4(
    uint32_t& r0, uint32_t& r1, uint32_t& r2, uint32_t& r3, uint32_t addr)
{
    asm volatile(
        "ldmatrix.sync.aligned.m8n8.x4.shared.b16 {%0,%1,%2,%3}, [%4];\n"
        : "=r"(r0), "=r"(r1), "=r"(r2), "=r"(r3) : "r"(addr));
}

__device__ __forceinline__ void cpa16(uint32_t dst, const void* src)
{
    asm volatile("cp.async.cg.shared.global [%0], [%1], 16;\n" :: "r"(dst), "l"(src));
}
__device__ __forceinline__ void cpa_commit()
{
    asm volatile("cp.async.commit_group;\n" ::: "memory");
}
__device__ __forceinline__ void cpa_wait0()
{
    asm volatile("cp.async.wait_group 0;\n" ::: "memory");
}

// ---------------------------------------------------------------------------
// Weight + bias convert.
// ---------------------------------------------------------------------------
__global__ void wconv_kernel(
    const float* __restrict__ Wq, const float* __restrict__ bq,
    const float* __restrict__ Wk, const float* __restrict__ bk,
    const float* __restrict__ Wv, const float* __restrict__ bv)
{
    const int gid = blockIdx.x * 256 + threadIdx.x;
    for (int i = gid; i < MROWS * CDIM; i += gridDim.x * 256) {
        const int row = i >> 8, col = i & 255;
        float v;
        if (row < 32)       v = Wq[row * CDIM + col];
        else if (row < 64)  v = Wk[(row - 32) * CDIM + col];
        else                v = Wv[(row - 64) * CDIM + col];
        g_Wh[i] = __float2half_rn(v);
    }
    if (gid < MROWS) {
        g_ball[gid] = (gid < 32) ? bq[gid] : (gid < 64) ? bk[gid - 32] : bv[gid - 64];
    }
}

// ---------------------------------------------------------------------------
// x transpose+convert: x [B][C][N] fp32 -> g_xhT [B][N][C] fp16.
// ---------------------------------------------------------------------------
__global__ __launch_bounds__(256) void xconv_kernel(const float* __restrict__ x)
{
    __shared__ __half ts[32 * 40];
    const int b  = blockIdx.z;
    const int c0 = blockIdx.y * 32;
    const int n0 = blockIdx.x * 32;
    const int tid = threadIdx.x;

#pragma unroll
    for (int it = 0; it < 4; it++) {
        const int idx = tid + 256 * it;
        const int cr = idx >> 5, nc = idx & 31;
        ts[nc * 40 + cr] =
            __float2half_rn(x[((size_t)b * CDIM + c0 + cr) * NPIX + n0 + nc]);
    }
    __syncthreads();
    if (tid < 128) {
        const int r = tid >> 2, sg = tid & 3;
        *(uint4*)&g_xhT[((size_t)b * NPIX + n0 + r) * CDIM + c0 + sg * 8] =
            *(const uint4*)&ts[r * 40 + sg * 8];
    }
}

// ---------------------------------------------------------------------------
// Projection GEMM (fp16 HMMA, fp32 acc). Q output pre-scaled by log2(e).
// ---------------------------------------------------------------------------
#define GP 72

__global__ __launch_bounds__(256, 2) void proj_gemm_kernel()
{
    __shared__ __align__(16) char smraw[(64 + 128) * GP * 2];
    __half* Wa = (__half*)smraw;
    __half* Xb = (__half*)(smraw + 64 * GP * 2);

    const int n0 = blockIdx.x * 128;
    const int b  = blockIdx.y;
    const int m0 = blockIdx.z * 64;
    const int tid = threadIdx.x;
    const int w = tid >> 5, lane = tid & 31;
    const int g = lane >> 2, t = lane & 3;
    const int mw = 32 * (w & 1);
    const int nw = 32 * (w >> 1);

    float acc[2][4][4];
#pragma unroll
    for (int i = 0; i < 2; i++)
#pragma unroll
        for (int j = 0; j < 4; j++)
#pragma unroll
            for (int k = 0; k < 4; k++) acc[i][j][k] = 0.f;

    for (int kc = 0; kc < 4; kc++) {
        __syncthreads();
#pragma unroll
        for (int r = 0; r < 2; r++) {
            const int idx = tid + 256 * r;
            const int row = idx >> 3, seg = idx & 7;
            *(uint4*)&Wa[row * GP + seg * 8] =
                *(const uint4*)&g_Wh[(m0 + row) * CDIM + kc * 64 + seg * 8];
        }
#pragma unroll
        for (int r = 0; r < 4; r++) {
            const int idx = tid + 256 * r;
            const int row = idx >> 3, seg = idx & 7;
            *(uint4*)&Xb[row * GP + seg * 8] =
                *(const uint4*)&g_xhT[((size_t)b * NPIX + n0 + row) * CDIM + kc * 64 + seg * 8];
        }
        __syncthreads();

#pragma unroll
        for (int s = 0; s < 4; s++) {
            uint32_t a[2][4];
#pragma unroll
            for (int i = 0; i < 2; i++) {
                const __half* base = &Wa[(mw + 16 * i + g) * GP + 2 * t + 16 * s];
                a[i][0] = *(const uint32_t*)base;
                a[i][2] = *(const uint32_t*)(base + 8);
                const __half* b8 = base + 8 * GP;
                a[i][1] = *(const uint32_t*)b8;
                a[i][3] = *(const uint32_t*)(b8 + 8);
            }
#pragma unroll
            for (int j = 0; j < 4; j++) {
                const __half* kb = &Xb[(nw + 8 * j + g) * GP + 2 * t + 16 * s];
                const uint32_t b0 = *(const uint32_t*)kb;
                const uint32_t b1 = *(const uint32_t*)(kb + 8);
                mma16816(acc[0][j][0], acc[0][j][1], acc[0][j][2], acc[0][j][3],
                         a[0][0], a[0][1], a[0][2], a[0][3], b0, b1);
                mma16816(acc[1][j][0], acc[1][j][1], acc[1][j][2], acc[1][j][3],
                         a[1][0], a[1][1], a[1][2], a[1][3], b0, b1);
            }
        }
    }

    if (m0 >= 64) {
#pragma unroll
        for (int i = 0; i < 2; i++) {
            const int r0 = mw + 16 * i + g;
            const int r1 = r0 + 8;
            const float bb0 = g_ball[m0 + r0];
            const float bb1 = g_ball[m0 + r1];
            const size_t c0g = (size_t)b * CDIM + (m0 - 64 + r0);
            const size_t c1g = (size_t)b * CDIM + (m0 - 64 + r1);
#pragma unroll
            for (int j = 0; j < 4; j++) {
                const int n = n0 + nw + 8 * j + 2 * t;
                *(__half2*)&g_VhT[c0g * NPIX + n] =
                    __floats2half2_rn(acc[i][j][0] + bb0, acc[i][j][1] + bb0);
                *(__half2*)&g_VhT[c1g * NPIX + n] =
                    __floats2half2_rn(acc[i][j][2] + bb1, acc[i][j][3] + bb1);
            }
        }
    } else {
        __half* Obuf = Xb;
        __syncthreads();
        // rows 0-31 = Q (scale by log2e), rows 32-63 = K (scale 1)
        const float qsc = (mw == 0) ? LOG2E : 1.0f;
#pragma unroll
        for (int i = 0; i < 2; i++) {
            const int r0 = mw + 16 * i + g;
            const int r1 = r0 + 8;
            const float bb0 = g_ball[r0];
            const float bb1 = g_ball[r1];
#pragma unroll
            for (int j = 0; j < 4; j++) {
                const int n = nw + 8 * j + 2 * t;
                Obuf[n * GP + r0]       = __float2half_rn((acc[i][j][0] + bb0) * qsc);
                Obuf[(n + 1) * GP + r0] = __float2half_rn((acc[i][j][1] + bb0) * qsc);
                Obuf[n * GP + r1]       = __float2half_rn((acc[i][j][2] + bb1) * qsc);
                Obuf[(n + 1) * GP + r1] = __float2half_rn((acc[i][j][3] + bb1) * qsc);
            }
        }
        __syncthreads();
#pragma unroll
        for (int r = 0; r < 2; r++) {
            const int idx = tid + 256 * r;
            const int n = idx >> 2, seg = idx & 3;
            *(uint4*)&g_Qh[((size_t)b * NPIX + n0 + n) * CQK + seg * 8] =
                *(const uint4*)&Obuf[n * GP + seg * 8];
            *(uint4*)&g_Kh[((size_t)b * NPIX + n0 + n) * CQK + seg * 8] =
                *(const uint4*)&Obuf[n * GP + 32 + seg * 8];
        }
    }
}

// ---------------------------------------------------------------------------
// Flash attention v3: register softmax + ldmatrix fragment loads +
// cp.async double-buffered K/V tiles. Base-2 exponentials (Q pre-scaled).
// CTA: 64 queries, 8 warps. Warp w: query rows 16*(w&3).., channels 128*(w>>2)..
// ---------------------------------------------------------------------------
#define QTILE 64
#define KTILE 64
#define KP    40   // halves per K row (stride 80B: LDSM conflict-free)
#define VP    72   // halves per V^T row (stride 144B: LDSM conflict-free)
#define OFS_K0 0
#define OFS_V0 5120
#define OFS_K1 41984
#define OFS_V1 47104
#define ATT_SMEM 83968
#define OBP 66     // Obuf [256 c][66] floats (aliases buffers)

__global__ __launch_bounds__(256, 2) void attn_kernel(
    float* __restrict__ out, const float* __restrict__ gamma)
{
    extern __shared__ __align__(16) char sm[];
    const uint32_t smbase = (uint32_t)__cvta_generic_to_shared(sm);

    const int b   = blockIdx.y;
    const int q0  = blockIdx.x * QTILE;
    const int tid = threadIdx.x;
    const int w   = tid >> 5;
    const int lane = tid & 31;
    const int g = lane >> 2;
    const int t = lane & 3;

    const int qr = 16 * (w & 3);     // query row base for this warp
    const int ch = 128 * (w >> 2);   // channel half base

    // ldmatrix lane addressing: row (lane&7) of matrix (lane>>3)
    const int lrow = lane & 7, lmat = lane >> 3;
    const uint32_t k_lane_off = (uint32_t)(lrow * KP + 8 * lmat) * 2;
    const uint32_t v_lane_off = (uint32_t)(lrow * VP + 8 * lmat) * 2;

    const size_t bN = (size_t)b * NPIX;
    const size_t bC = (size_t)b * CDIM;

    // ---- Q fragments straight from global (one time; pre-scaled by log2e) ----
    uint32_t qa[2][4];
    {
        const __half* r0p = &g_Qh[(bN + q0 + qr + g) * CQK];
        const __half* r8p = r0p + 8 * CQK;
#pragma unroll
        for (int s = 0; s < 2; s++) {
            qa[s][0] = *(const uint32_t*)&r0p[16 * s + 2 * t];
            qa[s][1] = *(const uint32_t*)&r8p[16 * s + 2 * t];
            qa[s][2] = *(const uint32_t*)&r0p[16 * s + 8 + 2 * t];
            qa[s][3] = *(const uint32_t*)&r8p[16 * s + 8 + 2 * t];
        }
    }

    float acc[16][4];
#pragma unroll
    for (int j = 0; j < 16; j++)
#pragma unroll
        for (int k = 0; k < 4; k++) acc[j][k] = 0.f;

    float m0r = -INFINITY, m1r = -INFINITY;
    float l0 = 0.f, l1 = 0.f;

    // tile loader (cp.async, 16B chunks)
    const int krow = tid >> 2, kseg = tid & 3;
    auto issue_tile = [&](int buf, int m0g) {
        const uint32_t kb = smbase + (buf ? OFS_K1 : OFS_K0);
        const uint32_t vb = smbase + (buf ? OFS_V1 : OFS_V0);
        cpa16(kb + krow * (KP * 2) + kseg * 16,
              &g_Kh[(bN + m0g + krow) * CQK + kseg * 8]);
#pragma unroll
        for (int it = 0; it < 8; it++) {
            const int idx = tid + 256 * it;
            const int c = idx >> 3, seg = idx & 7;
            cpa16(vb + c * (VP * 2) + seg * 16,
                  &g_VhT[(bC + c) * NPIX + m0g + seg * 8]);
        }
        cpa_commit();
    };

    issue_tile(0, 0);

    for (int kt = 0; kt < NPIX / KTILE; kt++) {
        const int buf = kt & 1;
        cpa_wait0();
        __syncthreads();                       // tile ready; prev reads done
        if (kt + 1 < NPIX / KTILE)
            issue_tile(buf ^ 1, (kt + 1) * KTILE);

        const uint32_t ks_u = smbase + (buf ? OFS_K1 : OFS_K0);
        const uint32_t vs_u = smbase + (buf ? OFS_V1 : OFS_V0);

        // ---- S = Q K^T : S[16][64] in registers; K frags via ldmatrix.x4 ----
        float sc[8][4];
#pragma unroll
        for (int j = 0; j < 8; j++) {
            uint32_t b00, b01, b10, b11;   // (s0:b0,b1) (s1:b0,b1)
            ldsm_x4(b00, b01, b10, b11, ks_u + j * (8 * KP * 2) + k_lane_off);
            float c0 = 0.f, c1 = 0.f, c2 = 0.f, c3 = 0.f;
            mma16816(c0, c1, c2, c3, qa[0][0], qa[0][1], qa[0][2], qa[0][3], b00, b01);
            mma16816(c0, c1, c2, c3, qa[1][0], qa[1][1], qa[1][2], qa[1][3], b10, b11);
            sc[j][0] = c0; sc[j][1] = c1; sc[j][2] = c2; sc[j][3] = c3;
        }

        // ---- online softmax in registers (base-2, quad shuffles) ----
        float mx0 = -INFINITY, mx1 = -INFINITY;
#pragma unroll
        for (int j = 0; j < 8; j++) {
            mx0 = fmaxf(mx0, fmaxf(sc[j][0], sc[j][1]));
            mx1 = fmaxf(mx1, fmaxf(sc[j][2], sc[j][3]));
        }
        mx0 = fmaxf(mx0, __shfl_xor_sync(0xffffffff, mx0, 1));
        mx0 = fmaxf(mx0, __shfl_xor_sync(0xffffffff, mx0, 2));
        mx1 = fmaxf(mx1, __shfl_xor_sync(0xffffffff, mx1, 1));
        mx1 = fmaxf(mx1, __shfl_xor_sync(0xffffffff, mx1, 2));

        const float mn0 = fmaxf(m0r, mx0);
        const float mn1 = fmaxf(m1r, mx1);
        const float al0 = ex2(m0r - mn0);
        const float al1 = ex2(m1r - mn1);
        m0r = mn0; m1r = mn1;

        uint32_t pa[4][4];
        float s0 = 0.f, s1 = 0.f;
#pragma unroll
        for (int s = 0; s < 4; s++) {
            {
                const int j = 2 * s;
                const float p00 = ex2(sc[j][0] - mn0);
                const float p01 = ex2(sc[j][1] - mn0);
                const float p10 = ex2(sc[j][2] - mn1);
                const float p11 = ex2(sc[j][3] - mn1);
                s0 += p00 + p01; s1 += p10 + p11;
                pa[s][0] = h2_as_u32(__floats2half2_rn(p00, p01));
                pa[s][1] = h2_as_u32(__floats2half2_rn(p10, p11));
            }
            {
                const int j = 2 * s + 1;
                const float p00 = ex2(sc[j][0] - mn0);
                const float p01 = ex2(sc[j][1] - mn0);
                const float p10 = ex2(sc[j][2] - mn1);
                const float p11 = ex2(sc[j][3] - mn1);
                s0 += p00 + p01; s1 += p10 + p11;
                pa[s][2] = h2_as_u32(__floats2half2_rn(p00, p01));
                pa[s][3] = h2_as_u32(__floats2half2_rn(p10, p11));
            }
        }
        s0 += __shfl_xor_sync(0xffffffff, s0, 1);
        s0 += __shfl_xor_sync(0xffffffff, s0, 2);
        s1 += __shfl_xor_sync(0xffffffff, s1, 1);
        s1 += __shfl_xor_sync(0xffffffff, s1, 2);
        l0 = l0 * al0 + s0;
        l1 = l1 * al1 + s1;

        // ---- rescale accumulators ----
#pragma unroll
        for (int j = 0; j < 16; j++) {
            acc[j][0] *= al0; acc[j][1] *= al0;
            acc[j][2] *= al1; acc[j][3] *= al1;
        }

        // ---- O += P V; V frags via ldmatrix.x4 (2 per jj row-block) ----
#pragma unroll
        for (int jj = 0; jj < 16; jj++) {
            const uint32_t rowb = vs_u + (ch + 8 * jj) * (VP * 2) + v_lane_off;
            uint32_t b0, b1, b2, b3, c0, c1, c2, c3;
            ldsm_x4(b0, b1, b2, b3, rowb);          // k 0..31  -> s0, s1
            ldsm_x4(c0, c1, c2, c3, rowb + 64);     // k 32..63 -> s2, s3
            mma16816(acc[jj][0], acc[jj][1], acc[jj][2], acc[jj][3],
                     pa[0][0], pa[0][1], pa[0][2], pa[0][3], b0, b1);
            mma16816(acc[jj][0], acc[jj][1], acc[jj][2], acc[jj][3],
                     pa[1][0], pa[1][1], pa[1][2], pa[1][3], b2, b3);
            mma16816(acc[jj][0], acc[jj][1], acc[jj][2], acc[jj][3],
                     pa[2][0], pa[2][1], pa[2][2], pa[2][3], c0, c1);
            mma16816(acc[jj][0], acc[jj][1], acc[jj][2], acc[jj][3],
                     pa[3][0], pa[3][1], pa[3][2], pa[3][3], c2, c3);
        }
    }

    // ---- epilogue: scale, transpose via smem, coalesced store ----
    const float gamma0 = gamma[0];
    const float inv0 = gamma0 / l0;
    const float inv1 = gamma0 / l1;

    float* Obuf = (float*)sm;   // [256 c][OBP]
    __syncthreads();            // everyone done reading V buffers
#pragma unroll
    for (int jj = 0; jj < 16; jj++) {
        const int c = ch + 8 * jj + 2 * t;
        const int r0 = qr + g;
        const int r1 = r0 + 8;
        Obuf[c * OBP + r0]       = acc[jj][0] * inv0;
        Obuf[(c + 1) * OBP + r0] = acc[jj][1] * inv0;
        Obuf[c * OBP + r1]       = acc[jj][2] * inv1;
        Obuf[(c + 1) * OBP + r1] = acc[jj][3] * inv1;
    }
    __syncthreads();
#pragma unroll
    for (int it = 0; it < 64; it++) {
        const int idx = tid + 256 * it;
        const int c = idx >> 6, q = idx & 63;
        out[(bC + c) * NPIX + q0 + q] = Obuf[c * OBP + q];
    }
}

// ---------------------------------------------------------------------------
// Inputs: x, Wq, bq, Wk, bk, Wv, bv, gamma. Output: float32 [B,C,H,W].
// ---------------------------------------------------------------------------
extern "C" void kernel_launch(void* const* d_in, const int* in_sizes, int n_in,
                              void* d_out, int out_size)
{
    const float* x     = (const float*)d_in[0];
    const float* Wq    = (const float*)d_in[1];
    const float* bq    = (const float*)d_in[2];
    const float* Wk    = (const float*)d_in[3];
    const float* bk    = (const float*)d_in[4];
    const float* Wv    = (const float*)d_in[5];
    const float* bv    = (const float*)d_in[6];
    const float* gamma = (const float*)d_in[7];
    float* out = (float*)d_out;

    cudaFuncSetAttribute(attn_kernel,
                         cudaFuncAttributeMaxDynamicSharedMemorySize, ATT_SMEM);

    wconv_kernel<<<80, 256>>>(Wq, bq, Wk, bk, Wv, bv);
    xconv_kernel<<<dim3(NPIX / 32, CDIM / 32, BATCH), 256>>>(x);
    proj_gemm_kernel<<<dim3(NPIX / 128, BATCH, 5), 256>>>();
    attn_kernel<<<dim3(NPIX / QTILE, BATCH), 256, ATT_SMEM>>>(out, gamma);
}

// round 9
// speedup vs baseline: 1.1851x; 1.1851x over previous
#include <cuda_runtime.h>
#include <cuda_fp16.h>
#include <cuda_bf16.h>
#include <math.h>
#include <stdint.h>

#define BATCH 4
#define CDIM  256
#define CQK   32
#define NPIX  4096   // 64*64
#define MROWS 320    // 32 (Q) + 32 (K) + 256 (V)
#define LOG2E 1.4426950408889634f
#define ONES_H2 0x3C003C00u   // half2(1.0, 1.0)

// fp16 scratch (static device globals: allowed)
__device__ __half g_Qh[BATCH * NPIX * CQK];    // Q pre-scaled by log2(e)
__device__ __half g_Kh[BATCH * NPIX * CQK];
__device__ __half g_VhT[(size_t)BATCH * CDIM * NPIX];   // [B][C][N]
__device__ __half g_xhT[(size_t)BATCH * NPIX * CDIM];   // [B][N][C]
__device__ __half g_Wh[MROWS * CDIM];                   // Wq|Wk|Wv stacked
__device__ float  g_ball[MROWS];

// ---------------------------------------------------------------------------
// helpers (defined BEFORE all uses)
// ---------------------------------------------------------------------------
__device__ __forceinline__ float ex2f(float x)
{
    float y;
    asm("ex2.approx.f32 %0, %1;" : "=f"(y) : "f"(x));
    return y;
}

// pack (lo, hi) fp32 -> half2, then 2^x elementwise. Returns half2 bits.
__device__ __forceinline__ uint32_t ex2_h2(float lo, float hi)
{
    uint32_t h;
    asm("cvt.rn.f16x2.f32 %0, %1, %2;" : "=r"(h) : "f"(hi), "f"(lo));
    asm("ex2.approx.f16x2 %0, %0;" : "+r"(h));
    return h;
}

__device__ __forceinline__ void mma16816(
    float& c0, float& c1, float& c2, float& c3,
    uint32_t a0, uint32_t a1, uint32_t a2, uint32_t a3,
    uint32_t b0, uint32_t b1)
{
    asm volatile(
        "mma.sync.aligned.m16n8k16.row.col.f32.f16.f16.f32 "
        "{%0,%1,%2,%3}, {%4,%5,%6,%7}, {%8,%9}, {%0,%1,%2,%3};\n"
        : "+f"(c0), "+f"(c1), "+f"(c2), "+f"(c3)
        : "r"(a0), "r"(a1), "r"(a2), "r"(a3), "r"(b0), "r"(b1));
}

__device__ __forceinline__ void cpa16(uint32_t dst, const void* src)
{
    asm volatile("cp.async.cg.shared.global [%0], [%1], 16;\n" :: "r"(dst), "l"(src));
}
__device__ __forceinline__ void cpa_commit()
{
    asm volatile("cp.async.commit_group;\n" ::: "memory");
}
__device__ __forceinline__ void cpa_wait0()
{
    asm volatile("cp.async.wait_group 0;\n" ::: "memory");
}

// ---------------------------------------------------------------------------
// Weight + bias convert.
// ---------------------------------------------------------------------------
__global__ void wconv_kernel(
    const float* __restrict__ Wq, const float* __restrict__ bq,
    const float* __restrict__ Wk, const float* __restrict__ bk,
    const float* __restrict__ Wv, const float* __restrict__ bv)
{
    const int gid = blockIdx.x * 256 + threadIdx.x;
    for (int i = gid; i < MROWS * CDIM; i += gridDim.x * 256) {
        const int row = i >> 8, col = i & 255;
        float v;
        if (row < 32)       v = Wq[row * CDIM + col];
        else if (row < 64)  v = Wk[(row - 32) * CDIM + col];
        else                v = Wv[(row - 64) * CDIM + col];
        g_Wh[i] = __float2half_rn(v);
    }
    if (gid < MROWS) {
        g_ball[gid] = (gid < 32) ? bq[gid] : (gid < 64) ? bk[gid - 32] : bv[gid - 64];
    }
}

// ---------------------------------------------------------------------------
// x transpose+convert: x [B][C][N] fp32 -> g_xhT [B][N][C] fp16.
// ---------------------------------------------------------------------------
__global__ __launch_bounds__(256) void xconv_kernel(const float* __restrict__ x)
{
    __shared__ __half ts[32 * 40];
    const int b  = blockIdx.z;
    const int c0 = blockIdx.y * 32;
    const int n0 = blockIdx.x * 32;
    const int tid = threadIdx.x;

#pragma unroll
    for (int it = 0; it < 4; it++) {
        const int idx = tid + 256 * it;
        const int cr = idx >> 5, nc = idx & 31;
        ts[nc * 40 + cr] =
            __float2half_rn(x[((size_t)b * CDIM + c0 + cr) * NPIX + n0 + nc]);
    }
    __syncthreads();
    if (tid < 128) {
        const int r = tid >> 2, sg = tid & 3;
        *(uint4*)&g_xhT[((size_t)b * NPIX + n0 + r) * CDIM + c0 + sg * 8] =
            *(const uint4*)&ts[r * 40 + sg * 8];
    }
}

// ---------------------------------------------------------------------------
// Projection GEMM (fp16 HMMA, fp32 acc). Q output pre-scaled by log2(e).
// ---------------------------------------------------------------------------
#define GP 72

__global__ __launch_bounds__(256, 2) void proj_gemm_kernel()
{
    __shared__ __align__(16) char smraw[(64 + 128) * GP * 2];
    __half* Wa = (__half*)smraw;
    __half* Xb = (__half*)(smraw + 64 * GP * 2);

    const int n0 = blockIdx.x * 128;
    const int b  = blockIdx.y;
    const int m0 = blockIdx.z * 64;
    const int tid = threadIdx.x;
    const int w = tid >> 5, lane = tid & 31;
    const int g = lane >> 2, t = lane & 3;
    const int mw = 32 * (w & 1);
    const int nw = 32 * (w >> 1);

    float acc[2][4][4];
#pragma unroll
    for (int i = 0; i < 2; i++)
#pragma unroll
        for (int j = 0; j < 4; j++)
#pragma unroll
            for (int k = 0; k < 4; k++) acc[i][j][k] = 0.f;

    for (int kc = 0; kc < 4; kc++) {
        __syncthreads();
#pragma unroll
        for (int r = 0; r < 2; r++) {
            const int idx = tid + 256 * r;
            const int row = idx >> 3, seg = idx & 7;
            *(uint4*)&Wa[row * GP + seg * 8] =
                *(const uint4*)&g_Wh[(m0 + row) * CDIM + kc * 64 + seg * 8];
        }
#pragma unroll
        for (int r = 0; r < 4; r++) {
            const int idx = tid + 256 * r;
            const int row = idx >> 3, seg = idx & 7;
            *(uint4*)&Xb[row * GP + seg * 8] =
                *(const uint4*)&g_xhT[((size_t)b * NPIX + n0 + row) * CDIM + kc * 64 + seg * 8];
        }
        __syncthreads();

#pragma unroll
        for (int s = 0; s < 4; s++) {
            uint32_t a[2][4];
#pragma unroll
            for (int i = 0; i < 2; i++) {
                const __half* base = &Wa[(mw + 16 * i + g) * GP + 2 * t + 16 * s];
                a[i][0] = *(const uint32_t*)base;
                a[i][2] = *(const uint32_t*)(base + 8);
                const __half* b8 = base + 8 * GP;
                a[i][1] = *(const uint32_t*)b8;
                a[i][3] = *(const uint32_t*)(b8 + 8);
            }
#pragma unroll
            for (int j = 0; j < 4; j++) {
                const __half* kb = &Xb[(nw + 8 * j + g) * GP + 2 * t + 16 * s];
                const uint32_t b0 = *(const uint32_t*)kb;
                const uint32_t b1 = *(const uint32_t*)(kb + 8);
                mma16816(acc[0][j][0], acc[0][j][1], acc[0][j][2], acc[0][j][3],
                         a[0][0], a[0][1], a[0][2], a[0][3], b0, b1);
                mma16816(acc[1][j][0], acc[1][j][1], acc[1][j][2], acc[1][j][3],
                         a[1][0], a[1][1], a[1][2], a[1][3], b0, b1);
            }
        }
    }

    if (m0 >= 64) {
#pragma unroll
        for (int i = 0; i < 2; i++) {
            const int r0 = mw + 16 * i + g;
            const int r1 = r0 + 8;
            const float bb0 = g_ball[m0 + r0];
            const float bb1 = g_ball[m0 + r1];
            const size_t c0g = (size_t)b * CDIM + (m0 - 64 + r0);
            const size_t c1g = (size_t)b * CDIM + (m0 - 64 + r1);
#pragma unroll
            for (int j = 0; j < 4; j++) {
                const int n = n0 + nw + 8 * j + 2 * t;
                *(__half2*)&g_VhT[c0g * NPIX + n] =
                    __floats2half2_rn(acc[i][j][0] + bb0, acc[i][j][1] + bb0);
                *(__half2*)&g_VhT[c1g * NPIX + n] =
                    __floats2half2_rn(acc[i][j][2] + bb1, acc[i][j][3] + bb1);
            }
        }
    } else {
        __half* Obuf = Xb;
        __syncthreads();
        // rows 0-31 = Q (scale by log2e), rows 32-63 = K (scale 1)
        const float qsc = (mw == 0) ? LOG2E : 1.0f;
#pragma unroll
        for (int i = 0; i < 2; i++) {
            const int r0 = mw + 16 * i + g;
            const int r1 = r0 + 8;
            const float bb0 = g_ball[r0];
            const float bb1 = g_ball[r1];
#pragma unroll
            for (int j = 0; j < 4; j++) {
                const int n = nw + 8 * j + 2 * t;
                Obuf[n * GP + r0]       = __float2half_rn((acc[i][j][0] + bb0) * qsc);
                Obuf[(n + 1) * GP + r0] = __float2half_rn((acc[i][j][1] + bb0) * qsc);
                Obuf[n * GP + r1]       = __float2half_rn((acc[i][j][2] + bb1) * qsc);
                Obuf[(n + 1) * GP + r1] = __float2half_rn((acc[i][j][3] + bb1) * qsc);
            }
        }
        __syncthreads();
#pragma unroll
        for (int r = 0; r < 2; r++) {
            const int idx = tid + 256 * r;
            const int n = idx >> 2, seg = idx & 3;
            *(uint4*)&g_Qh[((size_t)b * NPIX + n0 + n) * CQK + seg * 8] =
                *(const uint4*)&Obuf[n * GP + seg * 8];
            *(uint4*)&g_Kh[((size_t)b * NPIX + n0 + n) * CQK + seg * 8] =
                *(const uint4*)&Obuf[n * GP + 32 + seg * 8];
        }
    }
}

// ---------------------------------------------------------------------------
// Flash attention v4: register softmax (base-2, f16x2 ex2), ones-MMA row sums,
// scalar-LDS fragment loads (R7 layout), cp.async double-buffered K/V tiles.
// CTA: 64 queries, 8 warps. Warp w: query rows 16*(w&3).., channels 128*(w>>2)..
// ---------------------------------------------------------------------------
#define QTILE 64
#define KTILE 64
#define KP    40   // halves per K row
#define VP    72   // halves per V^T row
#define OFS_K0 0
#define OFS_V0 5120
#define OFS_K1 41984
#define OFS_V1 47104
#define ATT_SMEM 83968
#define OBP 66     // Obuf [256 c][66] floats (aliases buffers)

__global__ __launch_bounds__(256, 2) void attn_kernel(
    float* __restrict__ out, const float* __restrict__ gamma)
{
    extern __shared__ __align__(16) char sm[];
    const uint32_t smbase = (uint32_t)__cvta_generic_to_shared(sm);

    const int b   = blockIdx.y;
    const int q0  = blockIdx.x * QTILE;
    const int tid = threadIdx.x;
    const int w   = tid >> 5;
    const int lane = tid & 31;
    const int g = lane >> 2;
    const int t = lane & 3;

    const int qr = 16 * (w & 3);     // query row base for this warp
    const int ch = 128 * (w >> 2);   // channel half base

    const size_t bN = (size_t)b * NPIX;
    const size_t bC = (size_t)b * CDIM;

    // ---- Q fragments straight from global (one time; pre-scaled by log2e) ----
    uint32_t qa[2][4];
    {
        const __half* r0p = &g_Qh[(bN + q0 + qr + g) * CQK];
        const __half* r8p = r0p + 8 * CQK;
#pragma unroll
        for (int s = 0; s < 2; s++) {
            qa[s][0] = *(const uint32_t*)&r0p[16 * s + 2 * t];
            qa[s][1] = *(const uint32_t*)&r8p[16 * s + 2 * t];
            qa[s][2] = *(const uint32_t*)&r0p[16 * s + 8 + 2 * t];
            qa[s][3] = *(const uint32_t*)&r8p[16 * s + 8 + 2 * t];
        }
    }

    float acc[16][4];
#pragma unroll
    for (int j = 0; j < 16; j++)
#pragma unroll
        for (int k = 0; k < 4; k++) acc[j][k] = 0.f;

    // l carried as ones-MMA accumulators: ao0/ao1 -> row qr+g, ao2/ao3 -> row qr+8+g
    float ao0 = 0.f, ao1 = 0.f, ao2 = 0.f, ao3 = 0.f;
    float m0r = -INFINITY, m1r = -INFINITY;

    // tile loader (cp.async, 16B chunks)
    const int krow = tid >> 2, kseg = tid & 3;
    auto issue_tile = [&](int buf, int m0g) {
        const uint32_t kb = smbase + (buf ? OFS_K1 : OFS_K0);
        const uint32_t vb = smbase + (buf ? OFS_V1 : OFS_V0);
        cpa16(kb + krow * (KP * 2) + kseg * 16,
              &g_Kh[(bN + m0g + krow) * CQK + kseg * 8]);
#pragma unroll
        for (int it = 0; it < 8; it++) {
            const int idx = tid + 256 * it;
            const int c = idx >> 3, seg = idx & 7;
            cpa16(vb + c * (VP * 2) + seg * 16,
                  &g_VhT[(bC + c) * NPIX + m0g + seg * 8]);
        }
        cpa_commit();
    };

    issue_tile(0, 0);

    for (int kt = 0; kt < NPIX / KTILE; kt++) {
        const int buf = kt & 1;
        cpa_wait0();
        __syncthreads();                       // tile ready; prev reads done
        if (kt + 1 < NPIX / KTILE)
            issue_tile(buf ^ 1, (kt + 1) * KTILE);

        const __half* Ks  = (const __half*)(sm + (buf ? OFS_K1 : OFS_K0));
        const __half* VsT = (const __half*)(sm + (buf ? OFS_V1 : OFS_V0));

        // ---- S = Q K^T : S[16][64] in registers (log2-scaled) ----
        float sc[8][4];
#pragma unroll
        for (int j = 0; j < 8; j++) {
            float c0 = 0.f, c1 = 0.f, c2 = 0.f, c3 = 0.f;
#pragma unroll
            for (int s = 0; s < 2; s++) {
                const __half* kb = &Ks[(8 * j + g) * KP + 2 * t + 16 * s];
                const uint32_t b0 = *(const uint32_t*)kb;
                const uint32_t b1 = *(const uint32_t*)(kb + 8);
                mma16816(c0, c1, c2, c3, qa[s][0], qa[s][1], qa[s][2], qa[s][3], b0, b1);
            }
            sc[j][0] = c0; sc[j][1] = c1; sc[j][2] = c2; sc[j][3] = c3;
        }

        // ---- online softmax in registers (base-2, quad shuffles for max) ----
        float mx0 = -INFINITY, mx1 = -INFINITY;
#pragma unroll
        for (int j = 0; j < 8; j++) {
            mx0 = fmaxf(mx0, fmaxf(sc[j][0], sc[j][1]));
            mx1 = fmaxf(mx1, fmaxf(sc[j][2], sc[j][3]));
        }
        mx0 = fmaxf(mx0, __shfl_xor_sync(0xffffffff, mx0, 1));
        mx0 = fmaxf(mx0, __shfl_xor_sync(0xffffffff, mx0, 2));
        mx1 = fmaxf(mx1, __shfl_xor_sync(0xffffffff, mx1, 1));
        mx1 = fmaxf(mx1, __shfl_xor_sync(0xffffffff, mx1, 2));

        const float mn0 = fmaxf(m0r, mx0);
        const float mn1 = fmaxf(m1r, mx1);
        const float al0 = ex2f(m0r - mn0);
        const float al1 = ex2f(m1r - mn1);
        m0r = mn0; m1r = mn1;

        // P = 2^(sc - mn), packed straight into fp16 A-fragments
        uint32_t pa[4][4];
#pragma unroll
        for (int s = 0; s < 4; s++) {
            const int j0 = 2 * s, j1 = 2 * s + 1;
            pa[s][0] = ex2_h2(sc[j0][0] - mn0, sc[j0][1] - mn0);
            pa[s][1] = ex2_h2(sc[j0][2] - mn1, sc[j0][3] - mn1);
            pa[s][2] = ex2_h2(sc[j1][0] - mn0, sc[j1][1] - mn0);
            pa[s][3] = ex2_h2(sc[j1][2] - mn1, sc[j1][3] - mn1);
        }

        // ---- rescale accumulators (incl. row-sum accumulators) ----
#pragma unroll
        for (int j = 0; j < 16; j++) {
            acc[j][0] *= al0; acc[j][1] *= al0;
            acc[j][2] *= al1; acc[j][3] *= al1;
        }
        ao0 *= al0; ao1 *= al0; ao2 *= al1; ao3 *= al1;

        // ---- row sums via ones-MMA (B fragment = all 1.0h, a constant) ----
#pragma unroll
        for (int s = 0; s < 4; s++)
            mma16816(ao0, ao1, ao2, ao3,
                     pa[s][0], pa[s][1], pa[s][2], pa[s][3], ONES_H2, ONES_H2);

        // ---- O += P V (scalar-LDS B fragments; R7 layout) ----
#pragma unroll
        for (int s = 0; s < 4; s++) {
#pragma unroll
            for (int jj = 0; jj < 16; jj++) {
                const __half* vb = &VsT[(ch + 8 * jj + g) * VP + 2 * t + 16 * s];
                const uint32_t b0 = *(const uint32_t*)vb;
                const uint32_t b1 = *(const uint32_t*)(vb + 8);
                mma16816(acc[jj][0], acc[jj][1], acc[jj][2], acc[jj][3],
                         pa[s][0], pa[s][1], pa[s][2], pa[s][3], b0, b1);
            }
        }
    }

    // ---- epilogue: scale, transpose via smem, coalesced store ----
    const float gamma0 = gamma[0];
    const float inv0 = gamma0 / ao0;   // row qr+g
    const float inv1 = gamma0 / ao2;   // row qr+8+g

    float* Obuf = (float*)sm;   // [256 c][OBP]
    __syncthreads();            // everyone done reading V buffers
#pragma unroll
    for (int jj = 0; jj < 16; jj++) {
        const int c = ch + 8 * jj + 2 * t;
        const int r0 = qr + g;
        const int r1 = r0 + 8;
        Obuf[c * OBP + r0]       = acc[jj][0] * inv0;
        Obuf[(c + 1) * OBP + r0] = acc[jj][1] * inv0;
        Obuf[c * OBP + r1]       = acc[jj][2] * inv1;
        Obuf[(c + 1) * OBP + r1] = acc[jj][3] * inv1;
    }
    __syncthreads();
#pragma unroll
    for (int it = 0; it < 64; it++) {
        const int idx = tid + 256 * it;
        const int c = idx >> 6, q = idx & 63;
        out[(bC + c) * NPIX + q0 + q] = Obuf[c * OBP + q];
    }
}

// ---------------------------------------------------------------------------
// Inputs: x, Wq, bq, Wk, bk, Wv, bv, gamma. Output: float32 [B,C,H,W].
// ---------------------------------------------------------------------------
extern "C" void kernel_launch(void* const* d_in, const int* in_sizes, int n_in,
                              void* d_out, int out_size)
{
    const float* x     = (const float*)d_in[0];
    const float* Wq    = (const float*)d_in[1];
    const float* bq    = (const float*)d_in[2];
    const float* Wk    = (const float*)d_in[3];
    const float* bk    = (const float*)d_in[4];
    const float* Wv    = (const float*)d_in[5];
    const float* bv    = (const float*)d_in[6];
    const float* gamma = (const float*)d_in[7];
    float* out = (float*)d_out;

    cudaFuncSetAttribute(attn_kernel,
                         cudaFuncAttributeMaxDynamicSharedMemorySize, ATT_SMEM);

    wconv_kernel<<<80, 256>>>(Wq, bq, Wk, bk, Wv, bv);
    xconv_kernel<<<dim3(NPIX / 32, CDIM / 32, BATCH), 256>>>(x);
    proj_gemm_kernel<<<dim3(NPIX / 128, BATCH, 5), 256>>>();
    attn_kernel<<<dim3(NPIX / QTILE, BATCH), 256, ATT_SMEM>>>(out, gamma);
}